// round 1
// baseline (speedup 1.0000x reference)
#include <cuda_runtime.h>

// Problem constants (fixed-shape problem)
static constexpr int Bn  = 8;
static constexpr int NA  = 262144;
static constexpr int Mg  = 100;
static constexpr int Cc  = 7;
static constexpr int GW  = 256;          // grid width (cells), cell = 4.0 units over [0,1024)
static constexpr int NCELLS = GW * GW;   // 65536
static constexpr int NWORDS = NA / 32;   // 8192 bitmap words per image

// ---- device scratch (no allocations allowed) ----
__device__ int                g_cellCount[NCELLS];
__device__ int                g_cellStart[NCELLS + 1];
__device__ int                g_cellCursor[NCELLS];
__device__ int                g_items[NA];
__device__ unsigned int       g_nonneg[Bn * NWORDS];       // bit set => some gt within computed d2 <= 9
__device__ unsigned long long g_best[Bn * Mg];             // packed (key_bits<<32)|anchor_idx
__device__ double             g_bceSum[Bn];
__device__ int                g_cntNonneg[Bn];

// ------------------------------------------------------------------
__global__ void k_init() {
    int i = blockIdx.x * blockDim.x + threadIdx.x;   // 65536 threads
    if (i < NCELLS)      g_cellCount[i] = 0;
    if (i < Bn * NWORDS) g_nonneg[i]    = 0u;
    if (i < Bn * Mg)     g_best[i]      = 0xFFFFFFFFFFFFFFFFULL;
    if (i < Bn) { g_bceSum[i] = 0.0; g_cntNonneg[i] = 0; }
}

__device__ __forceinline__ int cellOf(float x) {
    int c = (int)(x * 0.25f);
    return min(GW - 1, max(0, c));
}

__global__ void k_count(const float* __restrict__ anchors) {
    int n = blockIdx.x * blockDim.x + threadIdx.x;
    if (n >= NA) return;
    int cx = cellOf(anchors[2 * n]);
    int cy = cellOf(anchors[2 * n + 1]);
    atomicAdd(&g_cellCount[cy * GW + cx], 1);
}

__global__ void k_scan() {                // single block, 1024 threads, 64 cells each
    __shared__ int part[1024];
    int t = threadIdx.x;
    int base = t * 64;
    int s = 0;
    for (int j = 0; j < 64; j++) s += g_cellCount[base + j];
    part[t] = s;
    __syncthreads();
    for (int off = 1; off < 1024; off <<= 1) {
        int o = (t >= off) ? part[t - off] : 0;
        __syncthreads();
        part[t] += o;
        __syncthreads();
    }
    int run = part[t] - s;                // exclusive
    for (int j = 0; j < 64; j++) {
        int c = g_cellCount[base + j];
        g_cellStart[base + j]  = run;
        g_cellCursor[base + j] = run;
        run += c;
    }
    if (t == 1023) g_cellStart[NCELLS] = run;
}

__global__ void k_scatter(const float* __restrict__ anchors) {
    int n = blockIdx.x * blockDim.x + threadIdx.x;
    if (n >= NA) return;
    int cx = cellOf(anchors[2 * n]);
    int cy = cellOf(anchors[2 * n + 1]);
    int p = atomicAdd(&g_cellCursor[cy * GW + cx], 1);
    g_items[p] = n;
}

// ------------------------------------------------------------------
// sum of softplus over pred_cls, per image. softplus = max(x,0)+log1p(exp(-|x|))
__global__ void k_bce(const float* __restrict__ cls) {
    long long i = (long long)blockIdx.x * blockDim.x + threadIdx.x;   // one float4 per thread
    float4 v = reinterpret_cast<const float4*>(cls)[i];
    double s = 0.0;
    s += (double)(fmaxf(v.x, 0.f) + log1pf(expf(-fabsf(v.x))));
    s += (double)(fmaxf(v.y, 0.f) + log1pf(expf(-fabsf(v.y))));
    s += (double)(fmaxf(v.z, 0.f) + log1pf(expf(-fabsf(v.z))));
    s += (double)(fmaxf(v.w, 0.f) + log1pf(expf(-fabsf(v.w))));

    // block reduce (double)
    for (int o = 16; o; o >>= 1) s += __shfl_down_sync(0xffffffffu, s, o);
    __shared__ double sh[8];
    int lane = threadIdx.x & 31, w = threadIdx.x >> 5;
    if (lane == 0) sh[w] = s;
    __syncthreads();
    if (w == 0) {
        s = (lane < (blockDim.x >> 5)) ? sh[lane] : 0.0;
        for (int o = 4; o; o >>= 1) s += __shfl_down_sync(0xffffffffu, s, o);
        if (lane == 0) atomicAdd(&g_bceSum[blockIdx.x / 1792], s);   // 1792 blocks per image
    }
}

// ------------------------------------------------------------------
// One warp per (b,m): expanding-ring grid search.
// d2 arithmetic replicates the reference exactly:
//   gg = rn(rn(gx*gx)+rn(gy*gy)); aa likewise; dot = fma(gy,ay, rn(gx*ax));
//   d2 = rn(rn(gg+aa) - 2*dot)   (x2 exact)
__global__ void k_assign(const float* __restrict__ anchors,
                         const float* __restrict__ gt_boxes) {
    int warpId = (blockIdx.x * blockDim.x + threadIdx.x) >> 5;
    int lane = threadIdx.x & 31;
    if (warpId >= Bn * Mg) return;
    int b = warpId / Mg, m = warpId % Mg;

    const float* g = &gt_boxes[(b * Mg + m) * 4];
    float gx = __fmul_rn(__fadd_rn(g[0], g[2]), 0.5f);
    float gy = __fmul_rn(__fadd_rn(g[1], g[3]), 0.5f);
    float gg = __fadd_rn(__fmul_rn(gx, gx), __fmul_rn(gy, gy));
    int cx0 = cellOf(gx), cy0 = cellOf(gy);
    unsigned int* bm = &g_nonneg[b * NWORDS];

    unsigned long long best = 0xFFFFFFFFFFFFFFFFULL;
    for (int k = 0; k < GW; ++k) {
        int x0 = cx0 - k, x1 = cx0 + k, y0 = cy0 - k, y1 = cy0 + k;
        int ylo = max(y0, 0), yhi = min(y1, GW - 1);
        for (int cy = ylo; cy <= yhi; ++cy) {
            bool edgeRow = (cy == y0 || cy == y1);
            int xlo = max(x0, 0), xhi = min(x1, GW - 1);
            for (int cx = xlo; cx <= xhi; ++cx) {
                if (!edgeRow && cx != x0 && cx != x1) continue;   // ring cells only
                int c = cy * GW + cx;
                int s = g_cellStart[c], e = g_cellStart[c + 1];
                for (int i = s + lane; i < e; i += 32) {
                    int n = g_items[i];
                    float ax = anchors[2 * n], ay = anchors[2 * n + 1];
                    float aa  = __fadd_rn(__fmul_rn(ax, ax), __fmul_rn(ay, ay));
                    float dot = __fmaf_rn(gy, ay, __fmul_rn(gx, ax));
                    float d2  = __fsub_rn(__fadd_rn(gg, aa), __fadd_rn(dot, dot));
                    if (d2 <= 9.0f)
                        atomicOr(&bm[n >> 5], 1u << (n & 31));
                    float key = fmaxf(d2, 0.0f);  // clip(d2,0): ties -> lowest index via pack
                    unsigned long long pk =
                        ((unsigned long long)__float_as_uint(key) << 32) | (unsigned)n;
                    if (pk < best) best = pk;
                }
            }
        }
        // warp-reduce current best, then check termination
        unsigned long long r = best;
        #pragma unroll
        for (int off = 16; off; off >>= 1) {
            unsigned long long o = __shfl_xor_sync(0xffffffffu, r, off);
            if (o < r) r = o;
        }
        best = r;
        float bk = __uint_as_float((unsigned)(r >> 32));   // NaN while empty -> keep searching
        float tt = 4.0f * (float)k;                        // lower bound on dist of unseen rings
        // margin 2.0 covers |computed-true| rounding on both sides; 3.2 covers neg radius 3
        if (tt > 3.2f && (tt * tt - 2.0f > bk)) break;
    }
    if (lane == 0) g_best[warpId] = best;
}

// ------------------------------------------------------------------
__global__ void k_popc() {
    int i = blockIdx.x * blockDim.x + threadIdx.x;     // 65536 words, 256/block
    int v = __popc(g_nonneg[i]);
    for (int o = 16; o; o >>= 1) v += __shfl_down_sync(0xffffffffu, v, o);
    __shared__ int sh[8];
    int lane = threadIdx.x & 31, w = threadIdx.x >> 5;
    if (lane == 0) sh[w] = v;
    __syncthreads();
    if (w == 0) {
        v = (lane < 8) ? sh[lane] : 0;
        for (int o = 4; o; o >>= 1) v += __shfl_down_sync(0xffffffffu, v, o);
        if (lane == 0) atomicAdd(&g_cntNonneg[blockIdx.x >> 5], v);  // 32 blocks per image
    }
}

// ------------------------------------------------------------------
__device__ __forceinline__ void computeBox(int n, int b,
        const float* __restrict__ pred_reg, const float* __restrict__ anchors,
        const float* __restrict__ strides, float* box) {
    float s = strides[n];
    const float* r = &pred_reg[((size_t)b * NA + n) * 4];
    float ax = anchors[2 * n], ay = anchors[2 * n + 1];
    float cx = __fadd_rn(ax, __fmul_rn(r[0], s));
    float cy = __fadd_rn(ay, __fmul_rn(r[1], s));
    float w  = __fmul_rn(expf(r[2]), s);
    float h  = __fmul_rn(expf(r[3]), s);
    float w2 = __fmul_rn(w, 0.5f), h2 = __fmul_rn(h, 0.5f);
    box[0] = __fsub_rn(cx, w2);
    box[1] = __fsub_rn(cy, h2);
    box[2] = __fadd_rn(cx, w2);
    box[3] = __fadd_rn(cy, h2);
}

__device__ __forceinline__ float giouLoss(const float* p, const float* g) {
    const float EPS = 1e-7f;
    float ap = __fmul_rn(__fsub_rn(p[2], p[0]), __fsub_rn(p[3], p[1]));
    float ag = __fmul_rn(__fsub_rn(g[2], g[0]), __fsub_rn(g[3], g[1]));
    float ltx = fmaxf(p[0], g[0]), lty = fmaxf(p[1], g[1]);
    float rbx = fminf(p[2], g[2]), rby = fminf(p[3], g[3]);
    float wx = fmaxf(__fsub_rn(rbx, ltx), 0.f), wy = fmaxf(__fsub_rn(rby, lty), 0.f);
    float inter = __fmul_rn(wx, wy);
    float uni = __fsub_rn(__fadd_rn(ap, ag), inter);
    float iou = __fdiv_rn(inter, __fadd_rn(uni, EPS));
    float lcx = fminf(p[0], g[0]), lcy = fminf(p[1], g[1]);
    float rcx = fmaxf(p[2], g[2]), rcy = fmaxf(p[3], g[3]);
    float wcx = fmaxf(__fsub_rn(rcx, lcx), 0.f), wcy = fmaxf(__fsub_rn(rcy, lcy), 0.f);
    float ac = __fmul_rn(wcx, wcy);
    float giou = __fsub_rn(iou, __fdiv_rn(__fsub_rn(ac, uni), __fadd_rn(ac, EPS)));
    return __fsub_rn(1.0f, giou);
}

__global__ void k_finalize(const float* __restrict__ pred_cls,
                           const float* __restrict__ pred_reg,
                           const float* __restrict__ anchors,
                           const float* __restrict__ strides,
                           const float* __restrict__ gt_boxes,
                           const int*   __restrict__ gt_labels,
                           float* out) {
    __shared__ int asg[Mg], srt[Mg], clsId[Mg];
    __shared__ float gtb[Mg][4], bx[Mg][4], bx2[Mg][4];
    __shared__ double sCorr, sPosW, sNe, sEq, lcTot, lbTot;
    __shared__ int sDistinct;
    int t = threadIdx.x;   // 128 threads
    if (t == 0) { lcTot = 0.0; lbTot = 0.0; }
    for (int b = 0; b < Bn; b++) {
        __syncthreads();
        if (t == 0) { sCorr = 0; sPosW = 0; sNe = 0; sEq = 0; sDistinct = 0; }
        if (t < Mg) {
            asg[t] = (int)(unsigned)(g_best[b * Mg + t] & 0xFFFFFFFFULL);
            int l = gt_labels[b * Mg + t] - 1;
            clsId[t] = min(max(l, 0), Cc - 1);
            #pragma unroll
            for (int j = 0; j < 4; j++) gtb[t][j] = gt_boxes[(b * Mg + t) * 4 + j];
        }
        __syncthreads();
        if (t < Mg) {
            int a = asg[t], c = clsId[t];
            bool dupA = false, dupAC = false;
            for (int u = 0; u < t; u++) {
                if (asg[u] == a) { dupA = true; if (clsId[u] == c) dupAC = true; }
            }
            if (!dupA) {
                atomicAdd(&sDistinct, 1);
                unsigned bit = (g_nonneg[b * NWORDS + (a >> 5)] >> (a & 31)) & 1u;
                atomicAdd(&sPosW, bit ? 0.1 : 1.0);   // wneg at pos anchors (extra x1 from the x2)
            }
            if (!dupAC)
                atomicAdd(&sCorr, (double)pred_cls[((size_t)b * NA + a) * Cc + c]);
            // stable rank for jnp.sort(assigned)
            int r = 0;
            for (int u = 0; u < Mg; u++) {
                int au = asg[u];
                if (au < a || (au == a && u < t)) r++;
            }
            srt[r] = a;
            computeBox(a, b, pred_reg, anchors, strides, bx[t]);
        }
        __syncthreads();
        if (t < Mg) {
            computeBox(srt[t], b, pred_reg, anchors, strides, bx2[t]);
            atomicAdd(&sNe, (double)giouLoss(bx[t],  gtb[t]));
            atomicAdd(&sEq, (double)giouLoss(bx2[t], gtb[t]));
        }
        __syncthreads();
        if (t == 0) {
            int cnt = g_cntNonneg[b];
            double sumSw = (double)(NA - cnt) + 0.1 * (double)cnt + sPosW;
            double meanSw = sumSw / (double)NA;
            double bceMean = (g_bceSum[b] - sCorr) / ((double)NA * (double)Cc);
            lcTot += bceMean * meanSw;
            lbTot += (sDistinct == Mg ? sEq : sNe) * 0.01;   // /100
        }
    }
    __syncthreads();
    if (t == 0)
        out[0] = (float)(lcTot / (double)Bn + 2.0 * (lbTot / (double)Bn));
}

// ------------------------------------------------------------------
extern "C" void kernel_launch(void* const* d_in, const int* in_sizes, int n_in,
                              void* d_out, int out_size) {
    const float* pred_cls  = (const float*)d_in[0];
    const float* pred_reg  = (const float*)d_in[1];
    const float* anchors   = (const float*)d_in[2];
    const float* strides   = (const float*)d_in[3];
    const float* gt_boxes  = (const float*)d_in[4];
    const int*   gt_labels = (const int*)d_in[5];
    float* out = (float*)d_out;

    k_init<<<256, 256>>>();
    k_count<<<NA / 256, 256>>>(anchors);
    k_scan<<<1, 1024>>>();
    k_scatter<<<NA / 256, 256>>>(anchors);
    k_bce<<<(Bn * NA * Cc / 4) / 256, 256>>>(pred_cls);   // 14336 blocks
    k_assign<<<(Bn * Mg * 32) / 128, 128>>>(anchors, gt_boxes);  // 200 blocks, 1 warp per query
    k_popc<<<(Bn * NWORDS) / 256, 256>>>();
    k_finalize<<<1, 128>>>(pred_cls, pred_reg, anchors, strides, gt_boxes, gt_labels, out);
}

// round 2
// speedup vs baseline: 2.5881x; 2.5881x over previous
#include <cuda_runtime.h>

// Problem constants (fixed-shape problem)
static constexpr int Bn  = 8;
static constexpr int NA  = 262144;
static constexpr int Mg  = 100;
static constexpr int Cc  = 7;
static constexpr int GW  = 256;          // grid width (cells), cell = 4.0 units over [0,1024)
static constexpr int NCELLS = GW * GW;   // 65536
static constexpr int NWORDS = NA / 32;   // 8192 bitmap words per image

// k_bce geometry: floats per image = NA*Cc = 1,835,008 = 458,752 float4
static constexpr int F4_PER_IMG   = NA * Cc / 4;          // 458752
static constexpr int BCE_BLK_IMG  = 448;                  // blocks per image
static constexpr int BCE_THR_IMG  = BCE_BLK_IMG * 256;    // 114688 threads/img
static constexpr int BCE_F4_PER_T = F4_PER_IMG / BCE_THR_IMG; // 4

// ---- device scratch (no allocations allowed) ----
__device__ int                g_cellCount[NCELLS];
__device__ int                g_cellStart[NCELLS + 1];
__device__ int                g_cellCursor[NCELLS];
__device__ int                g_items[NA];
__device__ unsigned int       g_nonneg[Bn * NWORDS];       // bit set => some gt with computed d2 <= 9
__device__ unsigned long long g_best[Bn * Mg];             // packed (key_bits<<32)|anchor_idx
__device__ double             g_bceSum[Bn];
__device__ int                g_cntNonneg[Bn];

// ------------------------------------------------------------------
__global__ void k_init() {
    int i = blockIdx.x * blockDim.x + threadIdx.x;   // 65536 threads
    if (i < NCELLS)      g_cellCount[i] = 0;
    if (i < Bn * NWORDS) g_nonneg[i]    = 0u;
    if (i < Bn * Mg)     g_best[i]      = 0xFFFFFFFFFFFFFFFFULL;
    if (i < Bn) { g_bceSum[i] = 0.0; g_cntNonneg[i] = 0; }
}

__device__ __forceinline__ int cellOf(float x) {
    int c = (int)(x * 0.25f);
    return min(GW - 1, max(0, c));
}

__global__ void k_count(const float2* __restrict__ anchors) {
    int n = blockIdx.x * blockDim.x + threadIdx.x;
    if (n >= NA) return;
    float2 a = anchors[n];
    atomicAdd(&g_cellCount[cellOf(a.y) * GW + cellOf(a.x)], 1);
}

// Warp-cooperative two-phase scan over 65536 counts. 1 block, 1024 threads.
__global__ void k_scan() {
    __shared__ int warpTot[32], warpBase[32];
    int t = threadIdx.x, lane = t & 31, w = t >> 5;
    int base0 = w * 2048;

    int s = 0;
    for (int j = 0; j < 64; j++) s += g_cellCount[base0 + j * 32 + lane];
    #pragma unroll
    for (int o = 16; o; o >>= 1) s += __shfl_xor_sync(0xffffffffu, s, o);
    if (lane == 0) warpTot[w] = s;
    __syncthreads();
    if (w == 0) {
        int v = warpTot[lane];
        int inc = v;
        #pragma unroll
        for (int o = 1; o < 32; o <<= 1) {
            int u = __shfl_up_sync(0xffffffffu, inc, o);
            if (lane >= o) inc += u;
        }
        warpBase[lane] = inc - v;
        if (lane == 31) g_cellStart[NCELLS] = inc;
    }
    __syncthreads();
    int run = warpBase[w];
    for (int j = 0; j < 64; j++) {
        int idx = base0 + j * 32 + lane;
        int c = g_cellCount[idx];
        int inc = c;
        #pragma unroll
        for (int o = 1; o < 32; o <<= 1) {
            int u = __shfl_up_sync(0xffffffffu, inc, o);
            if (lane >= o) inc += u;
        }
        int ex = run + inc - c;
        g_cellStart[idx]  = ex;
        g_cellCursor[idx] = ex;
        run += __shfl_sync(0xffffffffu, inc, 31);
    }
}

__global__ void k_scatter(const float2* __restrict__ anchors) {
    int n = blockIdx.x * blockDim.x + threadIdx.x;
    if (n >= NA) return;
    float2 a = anchors[n];
    int p = atomicAdd(&g_cellCursor[cellOf(a.y) * GW + cellOf(a.x)], 1);
    g_items[p] = n;
}

// ------------------------------------------------------------------
// softplus via raw MUFU: max(x,0) + ln2 * lg2(1 + 2^(-|x|*log2e))
__device__ __forceinline__ float sp(float x) {
    float a = fabsf(x) * -1.4426950408889634f;
    float e; asm("ex2.approx.f32 %0, %1;" : "=f"(e) : "f"(a));
    float l; asm("lg2.approx.f32 %0, %1;" : "=f"(l) : "f"(1.0f + e));
    return fmaxf(x, 0.0f) + 0.6931471805599453f * l;
}

// 3584 blocks x 256 threads; block group of 448 per image; coalesced strided reads.
__global__ void k_bce(const float4* __restrict__ cls) {
    int img = blockIdx.x / BCE_BLK_IMG;
    int bi  = blockIdx.x % BCE_BLK_IMG;
    const float4* p = cls + (size_t)img * F4_PER_IMG + bi * 256 + threadIdx.x;

    float acc = 0.0f;
    #pragma unroll
    for (int j = 0; j < BCE_F4_PER_T; j++) {
        float4 v = p[(size_t)j * BCE_THR_IMG];
        acc += (sp(v.x) + sp(v.y)) + (sp(v.z) + sp(v.w));
    }
    double s = (double)acc;
    #pragma unroll
    for (int o = 16; o; o >>= 1) s += __shfl_down_sync(0xffffffffu, s, o);
    __shared__ double sh[8];
    int lane = threadIdx.x & 31, w = threadIdx.x >> 5;
    if (lane == 0) sh[w] = s;
    __syncthreads();
    if (w == 0) {
        s = (lane < 8) ? sh[lane] : 0.0;
        #pragma unroll
        for (int o = 4; o; o >>= 1) s += __shfl_down_sync(0xffffffffu, s, o);
        if (lane == 0) atomicAdd(&g_bceSum[img], s);
    }
}

// ------------------------------------------------------------------
// d2 arithmetic replicates the reference bit-exactly (verified rel_err=0.0):
//   gg = rn(rn(gx*gx)+rn(gy*gy)); aa likewise; dot = fma(gy,ay, rn(gx*ax));
//   d2 = rn(rn(gg+aa) - rn(dot+dot))
__device__ __forceinline__ void scanCell(
        int c, int lane, float gx, float gy, float gg,
        const float2* __restrict__ anchors, unsigned int* bm,
        unsigned long long& best) {
    int s = g_cellStart[c], e = g_cellStart[c + 1];
    for (int i = s + lane; i < e; i += 32) {
        int n = g_items[i];
        float2 a = anchors[n];
        float aa  = __fadd_rn(__fmul_rn(a.x, a.x), __fmul_rn(a.y, a.y));
        float dot = __fmaf_rn(gy, a.y, __fmul_rn(gx, a.x));
        float d2  = __fsub_rn(__fadd_rn(gg, aa), __fadd_rn(dot, dot));
        if (d2 <= 9.0f)
            atomicOr(&bm[n >> 5], 1u << (n & 31));
        float key = fmaxf(d2, 0.0f);
        unsigned long long pk =
            ((unsigned long long)__float_as_uint(key) << 32) | (unsigned)n;
        if (pk < best) best = pk;
    }
}

__device__ __forceinline__ unsigned long long warpMin(unsigned long long v) {
    #pragma unroll
    for (int off = 16; off; off >>= 1) {
        unsigned long long o = __shfl_xor_sync(0xffffffffu, v, off);
        if (o < v) v = o;
    }
    return v;
}

// One warp per (b,m): unconditional 5x5 cell window (covers radius 8 true-dist;
// anchors outside have computed d2 >= 63-eps, and neg radius 3.2 << 8).
// Fallback expanding rings only if best found in window has key >= 62 or none found.
__global__ void k_assign(const float2* __restrict__ anchors,
                         const float* __restrict__ gt_boxes) {
    int warpId = (blockIdx.x * blockDim.x + threadIdx.x) >> 5;
    int lane = threadIdx.x & 31;
    if (warpId >= Bn * Mg) return;
    int b = warpId / Mg, m = warpId % Mg;

    const float* g = &gt_boxes[(b * Mg + m) * 4];
    float gx = __fmul_rn(__fadd_rn(g[0], g[2]), 0.5f);
    float gy = __fmul_rn(__fadd_rn(g[1], g[3]), 0.5f);
    float gg = __fadd_rn(__fmul_rn(gx, gx), __fmul_rn(gy, gy));
    int cx0 = cellOf(gx), cy0 = cellOf(gy);
    unsigned int* bm = &g_nonneg[b * NWORDS];

    unsigned long long best = 0xFFFFFFFFFFFFFFFFULL;
    int ylo = max(cy0 - 2, 0), yhi = min(cy0 + 2, GW - 1);
    int xlo = max(cx0 - 2, 0), xhi = min(cx0 + 2, GW - 1);
    for (int cy = ylo; cy <= yhi; ++cy)
        for (int cx = xlo; cx <= xhi; ++cx)
            scanCell(cy * GW + cx, lane, gx, gy, gg, anchors, bm, best);
    best = warpMin(best);

    // Fallback: only if window gave no safely-dominant winner (essentially never).
    float bk0 = __uint_as_float((unsigned)(best >> 32));
    if (!(bk0 < 62.0f)) {
        for (int k = 3; k < GW; ++k) {
            int x0 = cx0 - k, x1 = cx0 + k, y0 = cy0 - k, y1 = cy0 + k;
            int yl = max(y0, 0), yh = min(y1, GW - 1);
            for (int cy = yl; cy <= yh; ++cy) {
                bool edgeRow = (cy == y0 || cy == y1);
                int xl = max(x0, 0), xh = min(x1, GW - 1);
                for (int cx = xl; cx <= xh; ++cx) {
                    if (!edgeRow && cx != x0 && cx != x1) continue;
                    scanCell(cy * GW + cx, lane, gx, gy, gg, anchors, bm, best);
                }
            }
            best = warpMin(best);
            float bk = __uint_as_float((unsigned)(best >> 32));
            float tt = 4.0f * (float)k;
            if (bk < tt * tt - 2.0f) break;   // false for NaN -> keep searching
        }
    }
    if (lane == 0) g_best[warpId] = best;
}

// ------------------------------------------------------------------
__global__ void k_popc() {
    int i = blockIdx.x * blockDim.x + threadIdx.x;     // 65536 words
    int v = __popc(g_nonneg[i]);
    #pragma unroll
    for (int o = 16; o; o >>= 1) v += __shfl_down_sync(0xffffffffu, v, o);
    __shared__ int sh[8];
    int lane = threadIdx.x & 31, w = threadIdx.x >> 5;
    if (lane == 0) sh[w] = v;
    __syncthreads();
    if (w == 0) {
        v = (lane < 8) ? sh[lane] : 0;
        #pragma unroll
        for (int o = 4; o; o >>= 1) v += __shfl_down_sync(0xffffffffu, v, o);
        if (lane == 0) atomicAdd(&g_cntNonneg[blockIdx.x >> 5], v);  // 32 blocks/img
    }
}

// ------------------------------------------------------------------
__device__ __forceinline__ void computeBox(int n, int b,
        const float* __restrict__ pred_reg, const float* __restrict__ anchors,
        const float* __restrict__ strides, float* box) {
    float s = strides[n];
    const float* r = &pred_reg[((size_t)b * NA + n) * 4];
    float ax = anchors[2 * n], ay = anchors[2 * n + 1];
    float cx = __fadd_rn(ax, __fmul_rn(r[0], s));
    float cy = __fadd_rn(ay, __fmul_rn(r[1], s));
    float w  = __fmul_rn(expf(r[2]), s);
    float h  = __fmul_rn(expf(r[3]), s);
    float w2 = __fmul_rn(w, 0.5f), h2 = __fmul_rn(h, 0.5f);
    box[0] = __fsub_rn(cx, w2);
    box[1] = __fsub_rn(cy, h2);
    box[2] = __fadd_rn(cx, w2);
    box[3] = __fadd_rn(cy, h2);
}

__device__ __forceinline__ float giouLoss(const float* p, const float* g) {
    const float EPS = 1e-7f;
    float ap = __fmul_rn(__fsub_rn(p[2], p[0]), __fsub_rn(p[3], p[1]));
    float ag = __fmul_rn(__fsub_rn(g[2], g[0]), __fsub_rn(g[3], g[1]));
    float ltx = fmaxf(p[0], g[0]), lty = fmaxf(p[1], g[1]);
    float rbx = fminf(p[2], g[2]), rby = fminf(p[3], g[3]);
    float wx = fmaxf(__fsub_rn(rbx, ltx), 0.f), wy = fmaxf(__fsub_rn(rby, lty), 0.f);
    float inter = __fmul_rn(wx, wy);
    float uni = __fsub_rn(__fadd_rn(ap, ag), inter);
    float iou = __fdiv_rn(inter, __fadd_rn(uni, EPS));
    float lcx = fminf(p[0], g[0]), lcy = fminf(p[1], g[1]);
    float rcx = fmaxf(p[2], g[2]), rcy = fmaxf(p[3], g[3]);
    float wcx = fmaxf(__fsub_rn(rcx, lcx), 0.f), wcy = fmaxf(__fsub_rn(rcy, lcy), 0.f);
    float ac = __fmul_rn(wcx, wcy);
    float giou = __fsub_rn(iou, __fdiv_rn(__fsub_rn(ac, uni), __fadd_rn(ac, EPS)));
    return __fsub_rn(1.0f, giou);
}

__global__ void k_finalize(const float* __restrict__ pred_cls,
                           const float* __restrict__ pred_reg,
                           const float* __restrict__ anchors,
                           const float* __restrict__ strides,
                           const float* __restrict__ gt_boxes,
                           const int*   __restrict__ gt_labels,
                           float* out) {
    __shared__ int asg[Mg], srt[Mg], clsId[Mg];
    __shared__ float gtb[Mg][4], bx[Mg][4], bx2[Mg][4];
    __shared__ double sCorr, sPosW, sNe, sEq, lcTot, lbTot;
    __shared__ int sDistinct;
    int t = threadIdx.x;   // 128 threads
    if (t == 0) { lcTot = 0.0; lbTot = 0.0; }
    for (int b = 0; b < Bn; b++) {
        __syncthreads();
        if (t == 0) { sCorr = 0; sPosW = 0; sNe = 0; sEq = 0; sDistinct = 0; }
        if (t < Mg) {
            asg[t] = (int)(unsigned)(g_best[b * Mg + t] & 0xFFFFFFFFULL);
            int l = gt_labels[b * Mg + t] - 1;
            clsId[t] = min(max(l, 0), Cc - 1);
            #pragma unroll
            for (int j = 0; j < 4; j++) gtb[t][j] = gt_boxes[(b * Mg + t) * 4 + j];
        }
        __syncthreads();
        if (t < Mg) {
            int a = asg[t], c = clsId[t];
            bool dupA = false, dupAC = false;
            for (int u = 0; u < t; u++) {
                if (asg[u] == a) { dupA = true; if (clsId[u] == c) dupAC = true; }
            }
            if (!dupA) {
                atomicAdd(&sDistinct, 1);
                unsigned bit = (g_nonneg[b * NWORDS + (a >> 5)] >> (a & 31)) & 1u;
                atomicAdd(&sPosW, bit ? 0.1 : 1.0);
            }
            if (!dupAC)
                atomicAdd(&sCorr, (double)pred_cls[((size_t)b * NA + a) * Cc + c]);
            int r = 0;
            for (int u = 0; u < Mg; u++) {
                int au = asg[u];
                if (au < a || (au == a && u < t)) r++;
            }
            srt[r] = a;
            computeBox(a, b, pred_reg, anchors, strides, bx[t]);
        }
        __syncthreads();
        if (t < Mg) {
            computeBox(srt[t], b, pred_reg, anchors, strides, bx2[t]);
            atomicAdd(&sNe, (double)giouLoss(bx[t],  gtb[t]));
            atomicAdd(&sEq, (double)giouLoss(bx2[t], gtb[t]));
        }
        __syncthreads();
        if (t == 0) {
            int cnt = g_cntNonneg[b];
            double sumSw = (double)(NA - cnt) + 0.1 * (double)cnt + sPosW;
            double meanSw = sumSw / (double)NA;
            double bceMean = (g_bceSum[b] - sCorr) / ((double)NA * (double)Cc);
            lcTot += bceMean * meanSw;
            lbTot += (sDistinct == Mg ? sEq : sNe) * 0.01;
        }
    }
    __syncthreads();
    if (t == 0)
        out[0] = (float)(lcTot / (double)Bn + 2.0 * (lbTot / (double)Bn));
}

// ------------------------------------------------------------------
extern "C" void kernel_launch(void* const* d_in, const int* in_sizes, int n_in,
                              void* d_out, int out_size) {
    const float* pred_cls  = (const float*)d_in[0];
    const float* pred_reg  = (const float*)d_in[1];
    const float* anchors   = (const float*)d_in[2];
    const float* strides   = (const float*)d_in[3];
    const float* gt_boxes  = (const float*)d_in[4];
    const int*   gt_labels = (const int*)d_in[5];
    float* out = (float*)d_out;

    k_init<<<256, 256>>>();
    k_count<<<NA / 256, 256>>>((const float2*)anchors);
    k_scan<<<1, 1024>>>();
    k_scatter<<<NA / 256, 256>>>((const float2*)anchors);
    k_bce<<<Bn * BCE_BLK_IMG, 256>>>((const float4*)pred_cls);
    k_assign<<<(Bn * Mg * 32) / 128, 128>>>((const float2*)anchors, gt_boxes);
    k_popc<<<(Bn * NWORDS) / 256, 256>>>();
    k_finalize<<<1, 128>>>(pred_cls, pred_reg, anchors, strides, gt_boxes, gt_labels, out);
}

// round 3
// speedup vs baseline: 10.8017x; 4.1736x over previous
#include <cuda_runtime.h>

static constexpr int Bn  = 8;
static constexpr int NA  = 262144;
static constexpr int Mg  = 100;
static constexpr int Cc  = 7;
static constexpr int GW  = 128;          // cell = 8.0 units over [0,1024)
static constexpr int NCELLS = GW * GW;   // 16384
static constexpr int NWORDS = NA / 32;   // 8192 words per image

static constexpr int F4_PER_IMG   = NA * Cc / 4;           // 458752
static constexpr int BCE_BLK_IMG  = 448;
static constexpr int BCE_THR_IMG  = BCE_BLK_IMG * 256;     // 114688
static constexpr int BCE_F4_PER_T = F4_PER_IMG / BCE_THR_IMG; // 4
static constexpr int BCE_TOTAL    = Bn * BCE_BLK_IMG;      // 3584
static constexpr int BCE_S1 = 1195, BCE_S2 = 1195, BCE_S3 = BCE_TOTAL - BCE_S1 - BCE_S2;

// ---- device scratch ----
__device__ int                g_cellCount[NCELLS];
__device__ int                g_cellStart[NCELLS + 1];
__device__ int                g_cellCursor[NCELLS];
__device__ int                g_items[NA];
__device__ unsigned int       g_nonneg[Bn * NWORDS];
__device__ unsigned long long g_best[Bn * Mg];
__device__ double             g_bceSum[Bn];

// ------------------------------------------------------------------
__global__ void k_init() {
    int i = blockIdx.x * blockDim.x + threadIdx.x;   // 65536 threads
    if (i < NCELLS)      g_cellCount[i] = 0;
    if (i < Bn * NWORDS) g_nonneg[i]    = 0u;
    if (i < Bn * Mg)     g_best[i]      = 0xFFFFFFFFFFFFFFFFULL;
    if (i < Bn)          g_bceSum[i]    = 0.0;
}

__device__ __forceinline__ int cellOf(float x) {
    int c = (int)(x * 0.125f);
    return min(GW - 1, max(0, c));
}

// ---- bce block (softplus sum); called from fused kernels ----
__device__ __forceinline__ float sp(float x) {
    float a = fabsf(x) * -1.4426950408889634f;
    float e; asm("ex2.approx.f32 %0, %1;" : "=f"(e) : "f"(a));
    float l; asm("lg2.approx.f32 %0, %1;" : "=f"(l) : "f"(1.0f + e));
    return fmaxf(x, 0.0f) + 0.6931471805599453f * l;
}

__device__ void bceBlock(int gb, const float4* __restrict__ cls) {
    int img = gb / BCE_BLK_IMG;
    int bi  = gb % BCE_BLK_IMG;
    const float4* p = cls + (size_t)img * F4_PER_IMG + bi * 256 + threadIdx.x;
    float acc = 0.0f;
    #pragma unroll
    for (int j = 0; j < BCE_F4_PER_T; j++) {
        float4 v = p[(size_t)j * BCE_THR_IMG];
        acc += (sp(v.x) + sp(v.y)) + (sp(v.z) + sp(v.w));
    }
    double s = (double)acc;
    #pragma unroll
    for (int o = 16; o; o >>= 1) s += __shfl_down_sync(0xffffffffu, s, o);
    __shared__ double sh[8];
    int lane = threadIdx.x & 31, w = threadIdx.x >> 5;
    if (lane == 0) sh[w] = s;
    __syncthreads();
    if (w == 0) {
        s = (lane < 8) ? sh[lane] : 0.0;
        #pragma unroll
        for (int o = 4; o; o >>= 1) s += __shfl_down_sync(0xffffffffu, s, o);
        if (lane == 0) atomicAdd(&g_bceSum[img], s);
    }
}

// ------------------------------------------------------------------
__global__ void k_count_bce(const float2* __restrict__ anchors,
                            const float4* __restrict__ cls) {
    if (blockIdx.x < NA / 256) {
        int n = blockIdx.x * 256 + threadIdx.x;
        float2 a = anchors[n];
        atomicAdd(&g_cellCount[cellOf(a.y) * GW + cellOf(a.x)], 1);
    } else {
        bceBlock(blockIdx.x - NA / 256, cls);
    }
}

// Warp-cooperative two-phase scan over 16384 counts. 1 block, 1024 threads.
__global__ void k_scan() {
    __shared__ int warpTot[32], warpBase[32];
    int t = threadIdx.x, lane = t & 31, w = t >> 5;
    int base0 = w * 512;

    int s = 0;
    #pragma unroll
    for (int j = 0; j < 16; j++) s += g_cellCount[base0 + j * 32 + lane];
    #pragma unroll
    for (int o = 16; o; o >>= 1) s += __shfl_xor_sync(0xffffffffu, s, o);
    if (lane == 0) warpTot[w] = s;
    __syncthreads();
    if (w == 0) {
        int v = warpTot[lane];
        int inc = v;
        #pragma unroll
        for (int o = 1; o < 32; o <<= 1) {
            int u = __shfl_up_sync(0xffffffffu, inc, o);
            if (lane >= o) inc += u;
        }
        warpBase[lane] = inc - v;
        if (lane == 31) g_cellStart[NCELLS] = inc;
    }
    __syncthreads();
    int run = warpBase[w];
    for (int j = 0; j < 16; j++) {
        int idx = base0 + j * 32 + lane;
        int c = g_cellCount[idx];
        int inc = c;
        #pragma unroll
        for (int o = 1; o < 32; o <<= 1) {
            int u = __shfl_up_sync(0xffffffffu, inc, o);
            if (lane >= o) inc += u;
        }
        int ex = run + inc - c;
        g_cellStart[idx]  = ex;
        g_cellCursor[idx] = ex;
        run += __shfl_sync(0xffffffffu, inc, 31);
    }
}

__global__ void k_scatter_bce(const float2* __restrict__ anchors,
                              const float4* __restrict__ cls) {
    if (blockIdx.x < NA / 256) {
        int n = blockIdx.x * 256 + threadIdx.x;
        float2 a = anchors[n];
        int p = atomicAdd(&g_cellCursor[cellOf(a.y) * GW + cellOf(a.x)], 1);
        g_items[p] = n;
    } else {
        bceBlock(blockIdx.x - NA / 256 + BCE_S1, cls);
    }
}

// ------------------------------------------------------------------
// d2 arithmetic replicates the reference bit-exactly (verified rel_err=0.0)
__device__ __forceinline__ void scanCell(
        int c, int lane, float gx, float gy, float gg,
        const float2* __restrict__ anchors, unsigned int* bm,
        unsigned long long& best) {
    int s = g_cellStart[c], e = g_cellStart[c + 1];
    for (int i = s + lane; i < e; i += 32) {
        int n = g_items[i];
        float2 a = anchors[n];
        float aa  = __fadd_rn(__fmul_rn(a.x, a.x), __fmul_rn(a.y, a.y));
        float dot = __fmaf_rn(gy, a.y, __fmul_rn(gx, a.x));
        float d2  = __fsub_rn(__fadd_rn(gg, aa), __fadd_rn(dot, dot));
        if (d2 <= 9.0f)
            atomicOr(&bm[n >> 5], 1u << (n & 31));
        float key = fmaxf(d2, 0.0f);
        unsigned long long pk =
            ((unsigned long long)__float_as_uint(key) << 32) | (unsigned)n;
        if (pk < best) best = pk;
    }
}

__device__ __forceinline__ unsigned long long warpMin(unsigned long long v) {
    #pragma unroll
    for (int off = 16; off; off >>= 1) {
        unsigned long long o = __shfl_xor_sync(0xffffffffu, v, off);
        if (o < v) v = o;
    }
    return v;
}

// blocks [0,100): one warp per (b,m), 3x3-cell window (covers radius 8 > sqrt(62)).
// blocks [100,...): bce slice 3.
__global__ void k_assign_bce(const float2* __restrict__ anchors,
                             const float* __restrict__ gt_boxes,
                             const float4* __restrict__ cls) {
    if (blockIdx.x >= 100) { bceBlock(blockIdx.x - 100 + BCE_S1 + BCE_S2, cls); return; }
    int warpId = blockIdx.x * 8 + (threadIdx.x >> 5);   // 0..799
    int lane = threadIdx.x & 31;
    int b = warpId / Mg, m = warpId % Mg;

    const float* g = &gt_boxes[(b * Mg + m) * 4];
    float gx = __fmul_rn(__fadd_rn(g[0], g[2]), 0.5f);
    float gy = __fmul_rn(__fadd_rn(g[1], g[3]), 0.5f);
    float gg = __fadd_rn(__fmul_rn(gx, gx), __fmul_rn(gy, gy));
    int cx0 = cellOf(gx), cy0 = cellOf(gy);
    unsigned int* bm = &g_nonneg[b * NWORDS];

    unsigned long long best = 0xFFFFFFFFFFFFFFFFULL;
    int ylo = max(cy0 - 1, 0), yhi = min(cy0 + 1, GW - 1);
    int xlo = max(cx0 - 1, 0), xhi = min(cx0 + 1, GW - 1);
    for (int cy = ylo; cy <= yhi; ++cy)
        for (int cx = xlo; cx <= xhi; ++cx)
            scanCell(cy * GW + cx, lane, gx, gy, gg, anchors, bm, best);
    best = warpMin(best);

    float bk0 = __uint_as_float((unsigned)(best >> 32));
    if (!(bk0 < 62.0f)) {   // fallback (essentially never)
        for (int k = 2; k < GW; ++k) {
            int x0 = cx0 - k, x1 = cx0 + k, y0 = cy0 - k, y1 = cy0 + k;
            int yl = max(y0, 0), yh = min(y1, GW - 1);
            for (int cy = yl; cy <= yh; ++cy) {
                bool edgeRow = (cy == y0 || cy == y1);
                int xl = max(x0, 0), xh = min(x1, GW - 1);
                for (int cx = xl; cx <= xh; ++cx) {
                    if (!edgeRow && cx != x0 && cx != x1) continue;
                    scanCell(cy * GW + cx, lane, gx, gy, gg, anchors, bm, best);
                }
            }
            best = warpMin(best);
            float bk = __uint_as_float((unsigned)(best >> 32));
            float tt = 8.0f * (float)k;
            if (bk < tt * tt - 2.0f) break;
        }
    }
    if (lane == 0) g_best[warpId] = best;
}

// ------------------------------------------------------------------
__device__ __forceinline__ void computeBox(int n, int b,
        const float* __restrict__ pred_reg, const float* __restrict__ anchors,
        const float* __restrict__ strides, float* box) {
    float s = strides[n];
    const float* r = &pred_reg[((size_t)b * NA + n) * 4];
    float ax = anchors[2 * n], ay = anchors[2 * n + 1];
    float cx = __fadd_rn(ax, __fmul_rn(r[0], s));
    float cy = __fadd_rn(ay, __fmul_rn(r[1], s));
    float w  = __fmul_rn(expf(r[2]), s);
    float h  = __fmul_rn(expf(r[3]), s);
    float w2 = __fmul_rn(w, 0.5f), h2 = __fmul_rn(h, 0.5f);
    box[0] = __fsub_rn(cx, w2);
    box[1] = __fsub_rn(cy, h2);
    box[2] = __fadd_rn(cx, w2);
    box[3] = __fadd_rn(cy, h2);
}

__device__ __forceinline__ float giouLoss(const float* p, const float* g) {
    const float EPS = 1e-7f;
    float ap = __fmul_rn(__fsub_rn(p[2], p[0]), __fsub_rn(p[3], p[1]));
    float ag = __fmul_rn(__fsub_rn(g[2], g[0]), __fsub_rn(g[3], g[1]));
    float ltx = fmaxf(p[0], g[0]), lty = fmaxf(p[1], g[1]);
    float rbx = fminf(p[2], g[2]), rby = fminf(p[3], g[3]);
    float wx = fmaxf(__fsub_rn(rbx, ltx), 0.f), wy = fmaxf(__fsub_rn(rby, lty), 0.f);
    float inter = __fmul_rn(wx, wy);
    float uni = __fsub_rn(__fadd_rn(ap, ag), inter);
    float iou = __fdiv_rn(inter, __fadd_rn(uni, EPS));
    float lcx = fminf(p[0], g[0]), lcy = fminf(p[1], g[1]);
    float rcx = fmaxf(p[2], g[2]), rcy = fmaxf(p[3], g[3]);
    float wcx = fmaxf(__fsub_rn(rcx, lcx), 0.f), wcy = fmaxf(__fsub_rn(rcy, lcy), 0.f);
    float ac = __fmul_rn(wcx, wcy);
    float giou = __fsub_rn(iou, __fdiv_rn(__fsub_rn(ac, uni), __fadd_rn(ac, EPS)));
    return __fsub_rn(1.0f, giou);
}

// 1 block, 1024 threads: group g (=t/128) handles image g; no shared atomics.
__global__ void k_finalize(const float* __restrict__ pred_cls,
                           const float* __restrict__ pred_reg,
                           const float* __restrict__ anchors,
                           const float* __restrict__ strides,
                           const float* __restrict__ gt_boxes,
                           const int*   __restrict__ gt_labels,
                           float* out) {
    __shared__ int   asg[Bn][Mg], srt[Bn][Mg], clsId[Bn][Mg];
    __shared__ float gtb[Bn][Mg][4];
    __shared__ double rCorr[32], rPosW[32], rNe[32], rEq[32];
    __shared__ int   rDis[32], rCnt[32];
    __shared__ double lcA[Bn], lbA[Bn];

    int t = threadIdx.x;
    int g = t >> 7, r = t & 127;
    int lane = t & 31, w = t >> 5;

    // popc of this image's non-neg bitmap (64 coalesced words per thread)
    int cnt = 0;
    #pragma unroll 8
    for (int j = 0; j < 64; j++)
        cnt += __popc(g_nonneg[g * NWORDS + j * 128 + r]);

    if (r < Mg) {
        asg[g][r] = (int)(unsigned)(g_best[g * Mg + r] & 0xFFFFFFFFULL);
        int l = gt_labels[g * Mg + r] - 1;
        clsId[g][r] = min(max(l, 0), Cc - 1);
        #pragma unroll
        for (int j = 0; j < 4; j++) gtb[g][r][j] = gt_boxes[(g * Mg + r) * 4 + j];
    }
    __syncthreads();

    double corr = 0.0, posW = 0.0, ne = 0.0, eq = 0.0;
    int dis = 0;
    if (r < Mg) {
        int a = asg[g][r], c = clsId[g][r];
        bool dupA = false, dupAC = false;
        for (int u = 0; u < r; u++) {
            if (asg[g][u] == a) { dupA = true; if (clsId[g][u] == c) dupAC = true; }
        }
        if (!dupA) {
            dis = 1;
            unsigned bit = (g_nonneg[g * NWORDS + (a >> 5)] >> (a & 31)) & 1u;
            posW = bit ? 0.1 : 1.0;
        }
        if (!dupAC)
            corr = (double)pred_cls[((size_t)g * NA + a) * Cc + c];
        int rank = 0;
        for (int u = 0; u < Mg; u++) {
            int au = asg[g][u];
            if (au < a || (au == a && u < r)) rank++;
        }
        srt[g][rank] = a;
        float bx[4];
        computeBox(a, g, pred_reg, anchors, strides, bx);
        ne = (double)giouLoss(bx, gtb[g][r]);
    }
    __syncthreads();
    if (r < Mg) {
        float bx2[4];
        computeBox(srt[g][r], g, pred_reg, anchors, strides, bx2);
        eq = (double)giouLoss(bx2, gtb[g][r]);
    }

    // warp reductions
    #pragma unroll
    for (int o = 16; o; o >>= 1) {
        corr += __shfl_down_sync(0xffffffffu, corr, o);
        posW += __shfl_down_sync(0xffffffffu, posW, o);
        ne   += __shfl_down_sync(0xffffffffu, ne, o);
        eq   += __shfl_down_sync(0xffffffffu, eq, o);
        dis  += __shfl_down_sync(0xffffffffu, dis, o);
        cnt  += __shfl_down_sync(0xffffffffu, cnt, o);
    }
    if (lane == 0) {
        rCorr[w] = corr; rPosW[w] = posW; rNe[w] = ne; rEq[w] = eq;
        rDis[w] = dis; rCnt[w] = cnt;
    }
    __syncthreads();
    if (r == 0) {
        double C = 0, P = 0, Ne = 0, Eq = 0; int D = 0, Ct = 0;
        #pragma unroll
        for (int j = 0; j < 4; j++) {
            int ww = g * 4 + j;
            C += rCorr[ww]; P += rPosW[ww]; Ne += rNe[ww]; Eq += rEq[ww];
            D += rDis[ww]; Ct += rCnt[ww];
        }
        double sumSw = (double)(NA - Ct) + 0.1 * (double)Ct + P;
        double meanSw = sumSw / (double)NA;
        double bceMean = (g_bceSum[g] - C) / ((double)NA * (double)Cc);
        lcA[g] = bceMean * meanSw;
        lbA[g] = (D == Mg ? Eq : Ne) * 0.01;
    }
    __syncthreads();
    if (t == 0) {
        double lc = 0, lb = 0;
        #pragma unroll
        for (int b = 0; b < Bn; b++) { lc += lcA[b]; lb += lbA[b]; }
        out[0] = (float)(lc / (double)Bn + 2.0 * (lb / (double)Bn));
    }
}

// ------------------------------------------------------------------
extern "C" void kernel_launch(void* const* d_in, const int* in_sizes, int n_in,
                              void* d_out, int out_size) {
    const float* pred_cls  = (const float*)d_in[0];
    const float* pred_reg  = (const float*)d_in[1];
    const float* anchors   = (const float*)d_in[2];
    const float* strides   = (const float*)d_in[3];
    const float* gt_boxes  = (const float*)d_in[4];
    const int*   gt_labels = (const int*)d_in[5];
    float* out = (float*)d_out;

    k_init<<<256, 256>>>();
    k_count_bce<<<NA / 256 + BCE_S1, 256>>>((const float2*)anchors, (const float4*)pred_cls);
    k_scan<<<1, 1024>>>();
    k_scatter_bce<<<NA / 256 + BCE_S2, 256>>>((const float2*)anchors, (const float4*)pred_cls);
    k_assign_bce<<<100 + BCE_S3, 256>>>((const float2*)anchors, gt_boxes, (const float4*)pred_cls);
    k_finalize<<<1, 1024>>>(pred_cls, pred_reg, anchors, strides, gt_boxes, gt_labels, out);
}

// round 4
// speedup vs baseline: 13.1843x; 1.2206x over previous
#include <cuda_runtime.h>

static constexpr int Bn = 8;
static constexpr int NA = 262144;
static constexpr int Mg = 100;
static constexpr int Cc = 7;
static constexpr int GW = 128;            // cell = 8.0 units over [0,1024)
static constexpr int NCELLS = GW * GW;    // 16384
static constexpr int NWORDS = NA / 32;    // 8192 words per image
static constexpr int CAP = 64;            // bucket capacity (Poisson(16), overflow ~1e-18)

static constexpr int NB = 296;            // 2 blocks/SM on 148 SMs -> guaranteed co-resident
static constexpr int NT = 256;
static constexpr int NTHR = NB * NT;

static constexpr int F4_IMG   = NA * Cc / 4;   // 458752 float4 per image
static constexpr int CH_IMG   = 448;           // chunks/image (256 thr x 4 f4)
static constexpr int BLK_IMG  = 37;            // 296/8 blocks per image
static constexpr int J_STRIDE = 114688;        // f4 stride between j-slices

// ---- device scratch (static, no allocations) ----
__device__ int                g_cellCnt[NCELLS];
__device__ int                g_itemIdx[NCELLS * CAP];
__device__ float2             g_itemXY[NCELLS * CAP];
__device__ unsigned int       g_nonneg[Bn * NWORDS];
__device__ unsigned long long g_best[Bn * Mg];
__device__ double             g_bcePart[NB];
__device__ int                g_cnt[Bn];
__device__ unsigned int          g_barCnt = 0;
__device__ volatile unsigned int g_barGen = 0;

// ---- software grid barrier (all NB blocks guaranteed co-resident) ----
__device__ __forceinline__ void gridBarrier() {
    __syncthreads();
    if (threadIdx.x == 0) {
        unsigned gen = g_barGen;
        __threadfence();
        if (atomicAdd(&g_barCnt, 1u) == NB - 1) {
            g_barCnt = 0;
            __threadfence();
            g_barGen = gen + 1;
        } else {
            while (g_barGen == gen) __nanosleep(64);
        }
        __threadfence();
    }
    __syncthreads();
}

__device__ __forceinline__ int cellOf(float x) {
    int c = (int)(x * 0.125f);
    return min(GW - 1, max(0, c));
}

// softplus via raw MUFU (verified rel_err 0.0 vs reference aggregate)
__device__ __forceinline__ float sp(float x) {
    float a = fabsf(x) * -1.4426950408889634f;
    float e; asm("ex2.approx.f32 %0, %1;" : "=f"(e) : "f"(a));
    float l; asm("lg2.approx.f32 %0, %1;" : "=f"(l) : "f"(1.0f + e));
    return fmaxf(x, 0.0f) + 0.6931471805599453f * l;
}

// d2 arithmetic replicates the reference bit-exactly (verified rel_err=0.0)
__device__ __forceinline__ void scanCell(
        int c, int lane, float gx, float gy, float gg,
        unsigned int* bm, int& newBits, unsigned long long& best) {
    int cnt = min(g_cellCnt[c], CAP);
    int base = c * CAP;
    for (int i = lane; i < cnt; i += 32) {
        float2 a = g_itemXY[base + i];
        int n = g_itemIdx[base + i];
        float aa  = __fadd_rn(__fmul_rn(a.x, a.x), __fmul_rn(a.y, a.y));
        float dot = __fmaf_rn(gy, a.y, __fmul_rn(gx, a.x));
        float d2  = __fsub_rn(__fadd_rn(gg, aa), __fadd_rn(dot, dot));
        if (d2 <= 9.0f) {
            unsigned bit = 1u << (n & 31);
            unsigned old = atomicOr(&bm[n >> 5], bit);
            if (!(old & bit)) newBits++;
        }
        float key = fmaxf(d2, 0.0f);
        unsigned long long pk =
            ((unsigned long long)__float_as_uint(key) << 32) | (unsigned)n;
        if (pk < best) best = pk;
    }
}

__device__ __forceinline__ unsigned long long warpMin(unsigned long long v) {
    #pragma unroll
    for (int off = 16; off; off >>= 1) {
        unsigned long long o = __shfl_xor_sync(0xffffffffu, v, off);
        if (o < v) v = o;
    }
    return v;
}

__device__ __forceinline__ void computeBox(int n, int b,
        const float* __restrict__ pred_reg, const float* __restrict__ anchors,
        const float* __restrict__ strides, float* box) {
    float s = strides[n];
    const float* r = &pred_reg[((size_t)b * NA + n) * 4];
    float ax = anchors[2 * n], ay = anchors[2 * n + 1];
    float cx = __fadd_rn(ax, __fmul_rn(r[0], s));
    float cy = __fadd_rn(ay, __fmul_rn(r[1], s));
    float w  = __fmul_rn(expf(r[2]), s);
    float h  = __fmul_rn(expf(r[3]), s);
    float w2 = __fmul_rn(w, 0.5f), h2 = __fmul_rn(h, 0.5f);
    box[0] = __fsub_rn(cx, w2);
    box[1] = __fsub_rn(cy, h2);
    box[2] = __fadd_rn(cx, w2);
    box[3] = __fadd_rn(cy, h2);
}

__device__ __forceinline__ float giouLoss(const float* p, const float* g) {
    const float EPS = 1e-7f;
    float ap = __fmul_rn(__fsub_rn(p[2], p[0]), __fsub_rn(p[3], p[1]));
    float ag = __fmul_rn(__fsub_rn(g[2], g[0]), __fsub_rn(g[3], g[1]));
    float ltx = fmaxf(p[0], g[0]), lty = fmaxf(p[1], g[1]);
    float rbx = fminf(p[2], g[2]), rby = fminf(p[3], g[3]);
    float wx = fmaxf(__fsub_rn(rbx, ltx), 0.f), wy = fmaxf(__fsub_rn(rby, lty), 0.f);
    float inter = __fmul_rn(wx, wy);
    float uni = __fsub_rn(__fadd_rn(ap, ag), inter);
    float iou = __fdiv_rn(inter, __fadd_rn(uni, EPS));
    float lcx = fminf(p[0], g[0]), lcy = fminf(p[1], g[1]);
    float rcx = fmaxf(p[2], g[2]), rcy = fmaxf(p[3], g[3]);
    float wcx = fmaxf(__fsub_rn(rcx, lcx), 0.f), wcy = fmaxf(__fsub_rn(rcy, lcy), 0.f);
    float ac = __fmul_rn(wcx, wcy);
    float giou = __fsub_rn(iou, __fdiv_rn(__fsub_rn(ac, uni), __fadd_rn(ac, EPS)));
    return __fsub_rn(1.0f, giou);
}

// ==================================================================
__global__ void __launch_bounds__(NT, 2) k_all(
        const float2* __restrict__ anchors2, const float* __restrict__ anchors,
        const float4* __restrict__ cls4,     const float* __restrict__ cls,
        const float* __restrict__ pred_reg,  const float* __restrict__ strides,
        const float* __restrict__ gt_boxes,  const int* __restrict__ gt_labels,
        float* __restrict__ out) {
    const int b = blockIdx.x, t = threadIdx.x;
    const int gid = b * NT + t;

    __shared__ double shb[8];

    // ---- phase 0: zero scratch ----
    for (int i = gid; i < NCELLS; i += NTHR)      g_cellCnt[i] = 0;
    for (int i = gid; i < Bn * NWORDS; i += NTHR) g_nonneg[i] = 0u;
    if (gid < Bn) g_cnt[gid] = 0;
    gridBarrier();

    // ---- phase 1: bucket scatter + full bce stream ----
    for (int n = gid; n < NA; n += NTHR) {
        float2 a = anchors2[n];
        int cell = cellOf(a.y) * GW + cellOf(a.x);
        int p = atomicAdd(&g_cellCnt[cell], 1);
        if (p < CAP) { g_itemIdx[cell * CAP + p] = n; g_itemXY[cell * CAP + p] = a; }
    }
    {
        int g = b % Bn, li = b / Bn;          // 37 blocks per image
        const float4* base = cls4 + (size_t)g * F4_IMG;
        double acc = 0.0;
        for (int c = li; c < CH_IMG; c += BLK_IMG) {
            const float4* p = base + c * 256 + t;
            float a0 = 0.0f;
            #pragma unroll
            for (int j = 0; j < 4; j++) {
                float4 v = p[(size_t)j * J_STRIDE];
                a0 += (sp(v.x) + sp(v.y)) + (sp(v.z) + sp(v.w));
            }
            acc += (double)a0;
        }
        #pragma unroll
        for (int o = 16; o; o >>= 1) acc += __shfl_down_sync(0xffffffffu, acc, o);
        if ((t & 31) == 0) shb[t >> 5] = acc;
        __syncthreads();
        if (t == 0) {
            double s = 0.0;
            #pragma unroll
            for (int j = 0; j < 8; j++) s += shb[j];
            g_bcePart[b] = s;
        }
    }
    gridBarrier();

    // ---- phase 2: assignment (blocks 0..99, one warp per (img,gt)) ----
    if (b < 100) {
        int warpId = b * 8 + (t >> 5);        // 0..799
        int lane = t & 31;
        int img = warpId / Mg, m = warpId % Mg;

        const float* g = &gt_boxes[(img * Mg + m) * 4];
        float gx = __fmul_rn(__fadd_rn(g[0], g[2]), 0.5f);
        float gy = __fmul_rn(__fadd_rn(g[1], g[3]), 0.5f);
        float gg = __fadd_rn(__fmul_rn(gx, gx), __fmul_rn(gy, gy));
        int cx0 = cellOf(gx), cy0 = cellOf(gy);
        unsigned int* bm = &g_nonneg[img * NWORDS];

        int newBits = 0;
        unsigned long long best = 0xFFFFFFFFFFFFFFFFULL;
        int ylo = max(cy0 - 1, 0), yhi = min(cy0 + 1, GW - 1);
        int xlo = max(cx0 - 1, 0), xhi = min(cx0 + 1, GW - 1);
        for (int cy = ylo; cy <= yhi; ++cy)
            for (int cx = xlo; cx <= xhi; ++cx)
                scanCell(cy * GW + cx, lane, gx, gy, gg, bm, newBits, best);
        best = warpMin(best);

        float bk0 = __uint_as_float((unsigned)(best >> 32));
        if (!(bk0 < 62.0f)) {                 // fallback (essentially never)
            for (int k = 2; k < GW; ++k) {
                int x0 = cx0 - k, x1 = cx0 + k, y0 = cy0 - k, y1 = cy0 + k;
                int yl = max(y0, 0), yh = min(y1, GW - 1);
                for (int cy = yl; cy <= yh; ++cy) {
                    bool edgeRow = (cy == y0 || cy == y1);
                    int xl = max(x0, 0), xh = min(x1, GW - 1);
                    for (int cx = xl; cx <= xh; ++cx) {
                        if (!edgeRow && cx != x0 && cx != x1) continue;
                        scanCell(cy * GW + cx, lane, gx, gy, gg, bm, newBits, best);
                    }
                }
                best = warpMin(best);
                float bk = __uint_as_float((unsigned)(best >> 32));
                float tt = 8.0f * (float)k;
                if (bk < tt * tt - 2.0f) break;
            }
        }
        #pragma unroll
        for (int o = 16; o; o >>= 1) newBits += __shfl_down_sync(0xffffffffu, newBits, o);
        if (lane == 0) {
            g_best[warpId] = best;
            atomicAdd(&g_cnt[img], newBits);
        }
    }
    gridBarrier();

    // ---- phase 3: finalize (block 0 only; one warp per image) ----
    if (b != 0) return;
    __shared__ int   s_asg[Bn][Mg], s_cls[Bn][Mg], s_srt[Bn][Mg];
    __shared__ float s_gtb[Bn][Mg][4];
    __shared__ double s_lc[Bn], s_lb[Bn];

    int w = t >> 5, lane = t & 31;
    int g = w;   // warp w -> image g (8 warps)

    for (int m = lane; m < Mg; m += 32) {
        s_asg[g][m] = (int)(unsigned)(g_best[g * Mg + m] & 0xFFFFFFFFULL);
        int l = gt_labels[g * Mg + m] - 1;
        s_cls[g][m] = min(max(l, 0), Cc - 1);
        #pragma unroll
        for (int j = 0; j < 4; j++) s_gtb[g][m][j] = gt_boxes[(g * Mg + m) * 4 + j];
    }
    __syncwarp();

    double corr = 0.0, posW = 0.0, ne = 0.0, eq = 0.0;
    int dis = 0;
    for (int m = lane; m < Mg; m += 32) {
        int a = s_asg[g][m], c = s_cls[g][m];
        bool dupA = false, dupAC = false;
        for (int u = 0; u < m; u++) {
            int au = s_asg[g][u];
            if (au == a) { dupA = true; if (s_cls[g][u] == c) dupAC = true; }
        }
        if (!dupA) {
            dis++;
            unsigned bit = (g_nonneg[g * NWORDS + (a >> 5)] >> (a & 31)) & 1u;
            posW += bit ? 0.1 : 1.0;
        }
        if (!dupAC)
            corr += (double)cls[((size_t)g * NA + a) * Cc + c];
        int rank = 0;
        for (int u = 0; u < Mg; u++) {
            int au = s_asg[g][u];
            if (au < a || (au == a && u < m)) rank++;
        }
        s_srt[g][rank] = a;
        float bx[4];
        computeBox(a, g, pred_reg, anchors, strides, bx);
        ne += (double)giouLoss(bx, s_gtb[g][m]);
    }
    __syncwarp();
    for (int m = lane; m < Mg; m += 32) {
        float bx[4];
        computeBox(s_srt[g][m], g, pred_reg, anchors, strides, bx);
        eq += (double)giouLoss(bx, s_gtb[g][m]);
    }

    // bce partials for image g: blocks g + 8*li, li = 0..36
    double bce = g_bcePart[g + 8 * lane];
    if (lane < 5) bce += g_bcePart[g + 8 * (lane + 32)];

    #pragma unroll
    for (int o = 16; o; o >>= 1) {
        corr += __shfl_down_sync(0xffffffffu, corr, o);
        posW += __shfl_down_sync(0xffffffffu, posW, o);
        ne   += __shfl_down_sync(0xffffffffu, ne, o);
        eq   += __shfl_down_sync(0xffffffffu, eq, o);
        bce  += __shfl_down_sync(0xffffffffu, bce, o);
        dis  += __shfl_down_sync(0xffffffffu, dis, o);
    }
    if (lane == 0) {
        int cnt = g_cnt[g];
        double sumSw = (double)(NA - cnt) + 0.1 * (double)cnt + posW;
        double meanSw = sumSw / (double)NA;
        double bceMean = (bce - corr) / ((double)NA * (double)Cc);
        s_lc[g] = bceMean * meanSw;
        s_lb[g] = (dis == Mg ? eq : ne) * 0.01;
    }
    __syncthreads();
    if (t == 0) {
        double lc = 0.0, lb = 0.0;
        #pragma unroll
        for (int i = 0; i < Bn; i++) { lc += s_lc[i]; lb += s_lb[i]; }
        out[0] = (float)(lc / (double)Bn + 2.0 * (lb / (double)Bn));
    }
}

// ------------------------------------------------------------------
extern "C" void kernel_launch(void* const* d_in, const int* in_sizes, int n_in,
                              void* d_out, int out_size) {
    const float* pred_cls  = (const float*)d_in[0];
    const float* pred_reg  = (const float*)d_in[1];
    const float* anchors   = (const float*)d_in[2];
    const float* strides   = (const float*)d_in[3];
    const float* gt_boxes  = (const float*)d_in[4];
    const int*   gt_labels = (const int*)d_in[5];
    float* out = (float*)d_out;

    k_all<<<NB, NT>>>((const float2*)anchors, anchors,
                      (const float4*)pred_cls, pred_cls,
                      pred_reg, strides, gt_boxes, gt_labels, out);
}

// round 5
// speedup vs baseline: 13.5300x; 1.0262x over previous
#include <cuda_runtime.h>

static constexpr int Bn = 8;
static constexpr int NA = 262144;
static constexpr int Mg = 100;
static constexpr int Cc = 7;
static constexpr int GW = 128;            // cell = 8.0 units over [0,1024)
static constexpr int NCELLS = GW * GW;    // 16384
static constexpr int NWORDS = NA / 32;    // 8192 words per image
static constexpr int CAP = 64;            // bucket capacity (Poisson(16), overflow ~1e-18)

static constexpr int NB = 296;            // 2 blocks/SM on 148 SMs -> co-resident
static constexpr int NT = 512;            // 1024 thr/SM (54 regs -> fits 2 blocks/SM)
static constexpr int NTHR = NB * NT;      // 151552

static constexpr int F4_IMG  = NA * Cc / 4;    // 458752 float4 per image
static constexpr int CH_IMG  = 112;            // chunks/image (512 thr x 8 f4 = 4096 f4)
static constexpr int BLK_IMG = 37;             // blocks per image
static constexpr int J_STRIDE = 57344;         // f4 stride between j-slices (512*112)

// ---- device scratch (static, no allocations) ----
__device__ int                g_cellCnt[NCELLS];
__device__ int                g_itemIdx[NCELLS * CAP];
__device__ float2             g_itemXY[NCELLS * CAP];
__device__ unsigned int       g_nonneg[Bn * NWORDS];
__device__ unsigned long long g_best[Bn * Mg];
__device__ double             g_bcePart[NB];
__device__ int                g_cnt[Bn];
__device__ unsigned int          g_barCnt = 0;
__device__ volatile unsigned int g_barGen = 0;

// ---- software grid barrier (all NB blocks co-resident) ----
__device__ __forceinline__ void gridBarrier() {
    __syncthreads();
    if (threadIdx.x == 0) {
        unsigned gen = g_barGen;
        __threadfence();
        if (atomicAdd(&g_barCnt, 1u) == NB - 1) {
            g_barCnt = 0;
            __threadfence();
            g_barGen = gen + 1;
        } else {
            while (g_barGen == gen) __nanosleep(64);
        }
        __threadfence();
    }
    __syncthreads();
}

__device__ __forceinline__ int cellOf(float x) {
    int c = (int)(x * 0.125f);
    return min(GW - 1, max(0, c));
}

// softplus via raw MUFU (verified rel_err 0.0 vs reference aggregate)
__device__ __forceinline__ float sp(float x) {
    float a = fabsf(x) * -1.4426950408889634f;
    float e; asm("ex2.approx.f32 %0, %1;" : "=f"(e) : "f"(a));
    float l; asm("lg2.approx.f32 %0, %1;" : "=f"(l) : "f"(1.0f + e));
    return fmaxf(x, 0.0f) + 0.6931471805599453f * l;
}

// d2 arithmetic replicates the reference bit-exactly (verified rel_err=0.0)
__device__ __forceinline__ void scanCell(
        int c, int lane, float gx, float gy, float gg,
        unsigned int* bm, int& newBits, unsigned long long& best) {
    int cnt = min(g_cellCnt[c], CAP);
    int base = c * CAP;
    for (int i = lane; i < cnt; i += 32) {
        float2 a = g_itemXY[base + i];
        int n = g_itemIdx[base + i];
        float aa  = __fadd_rn(__fmul_rn(a.x, a.x), __fmul_rn(a.y, a.y));
        float dot = __fmaf_rn(gy, a.y, __fmul_rn(gx, a.x));
        float d2  = __fsub_rn(__fadd_rn(gg, aa), __fadd_rn(dot, dot));
        if (d2 <= 9.0f) {
            unsigned bit = 1u << (n & 31);
            unsigned old = atomicOr(&bm[n >> 5], bit);
            if (!(old & bit)) newBits++;
        }
        float key = fmaxf(d2, 0.0f);
        unsigned long long pk =
            ((unsigned long long)__float_as_uint(key) << 32) | (unsigned)n;
        if (pk < best) best = pk;
    }
}

__device__ __forceinline__ unsigned long long warpMin(unsigned long long v) {
    #pragma unroll
    for (int off = 16; off; off >>= 1) {
        unsigned long long o = __shfl_xor_sync(0xffffffffu, v, off);
        if (o < v) v = o;
    }
    return v;
}

__device__ __forceinline__ void computeBox(int n, int b,
        const float* __restrict__ pred_reg, const float* __restrict__ anchors,
        const float* __restrict__ strides, float* box) {
    float s = strides[n];
    const float* r = &pred_reg[((size_t)b * NA + n) * 4];
    float ax = anchors[2 * n], ay = anchors[2 * n + 1];
    float cx = __fadd_rn(ax, __fmul_rn(r[0], s));
    float cy = __fadd_rn(ay, __fmul_rn(r[1], s));
    float w  = __fmul_rn(expf(r[2]), s);
    float h  = __fmul_rn(expf(r[3]), s);
    float w2 = __fmul_rn(w, 0.5f), h2 = __fmul_rn(h, 0.5f);
    box[0] = __fsub_rn(cx, w2);
    box[1] = __fsub_rn(cy, h2);
    box[2] = __fadd_rn(cx, w2);
    box[3] = __fadd_rn(cy, h2);
}

__device__ __forceinline__ float giouLoss(const float* p, const float* g) {
    const float EPS = 1e-7f;
    float ap = __fmul_rn(__fsub_rn(p[2], p[0]), __fsub_rn(p[3], p[1]));
    float ag = __fmul_rn(__fsub_rn(g[2], g[0]), __fsub_rn(g[3], g[1]));
    float ltx = fmaxf(p[0], g[0]), lty = fmaxf(p[1], g[1]);
    float rbx = fminf(p[2], g[2]), rby = fminf(p[3], g[3]);
    float wx = fmaxf(__fsub_rn(rbx, ltx), 0.f), wy = fmaxf(__fsub_rn(rby, lty), 0.f);
    float inter = __fmul_rn(wx, wy);
    float uni = __fsub_rn(__fadd_rn(ap, ag), inter);
    float iou = __fdiv_rn(inter, __fadd_rn(uni, EPS));
    float lcx = fminf(p[0], g[0]), lcy = fminf(p[1], g[1]);
    float rcx = fmaxf(p[2], g[2]), rcy = fmaxf(p[3], g[3]);
    float wcx = fmaxf(__fsub_rn(rcx, lcx), 0.f), wcy = fmaxf(__fsub_rn(rcy, lcy), 0.f);
    float ac = __fmul_rn(wcx, wcy);
    float giou = __fsub_rn(iou, __fdiv_rn(__fsub_rn(ac, uni), __fadd_rn(ac, EPS)));
    return __fsub_rn(1.0f, giou);
}

// ==================================================================
__global__ void __launch_bounds__(NT, 2) k_all(
        const float2* __restrict__ anchors2, const float* __restrict__ anchors,
        const float4* __restrict__ cls4,     const float* __restrict__ cls,
        const float* __restrict__ pred_reg,  const float* __restrict__ strides,
        const float* __restrict__ gt_boxes,  const int* __restrict__ gt_labels,
        float* __restrict__ out) {
    const int b = blockIdx.x, t = threadIdx.x;
    const int gid = b * NT + t;

    __shared__ double shb[16];

    // ---- phase 0: zero scratch ----
    for (int i = gid; i < NCELLS; i += NTHR)      g_cellCnt[i] = 0;
    for (int i = gid; i < Bn * NWORDS; i += NTHR) g_nonneg[i] = 0u;
    if (gid < Bn) g_cnt[gid] = 0;
    gridBarrier();

    // ---- phase 1: bucket scatter + full bce stream ----
    for (int n = gid; n < NA; n += NTHR) {
        float2 a = anchors2[n];
        int cell = cellOf(a.y) * GW + cellOf(a.x);
        int p = atomicAdd(&g_cellCnt[cell], 1);
        if (p < CAP) { g_itemIdx[cell * CAP + p] = n; g_itemXY[cell * CAP + p] = a; }
    }
    {
        int g = b % Bn, li = b / Bn;          // 37 blocks per image
        const float4* base = cls4 + (size_t)g * F4_IMG;
        double acc = 0.0;
        for (int c = li; c < CH_IMG; c += BLK_IMG) {
            const float4* p = base + c * NT + t;
            float4 v[8];
            #pragma unroll
            for (int j = 0; j < 8; j++)       // 8 independent LDG.128 in flight
                v[j] = p[(size_t)j * J_STRIDE];
            float a0 = 0.0f;
            #pragma unroll
            for (int j = 0; j < 8; j++)
                a0 += (sp(v[j].x) + sp(v[j].y)) + (sp(v[j].z) + sp(v[j].w));
            acc += (double)a0;
        }
        #pragma unroll
        for (int o = 16; o; o >>= 1) acc += __shfl_down_sync(0xffffffffu, acc, o);
        if ((t & 31) == 0) shb[t >> 5] = acc;
        __syncthreads();
        if (t == 0) {
            double s = 0.0;
            #pragma unroll
            for (int j = 0; j < 16; j++) s += shb[j];
            g_bcePart[b] = s;
        }
    }
    gridBarrier();

    // ---- phase 2: assignment (blocks 0..49, one warp per (img,gt)) ----
    if (b < 50) {
        int warpId = b * 16 + (t >> 5);       // 0..799
        int lane = t & 31;
        int img = warpId / Mg, m = warpId % Mg;

        const float* g = &gt_boxes[(img * Mg + m) * 4];
        float gx = __fmul_rn(__fadd_rn(g[0], g[2]), 0.5f);
        float gy = __fmul_rn(__fadd_rn(g[1], g[3]), 0.5f);
        float gg = __fadd_rn(__fmul_rn(gx, gx), __fmul_rn(gy, gy));
        int cx0 = cellOf(gx), cy0 = cellOf(gy);
        unsigned int* bm = &g_nonneg[img * NWORDS];

        int newBits = 0;
        unsigned long long best = 0xFFFFFFFFFFFFFFFFULL;
        int ylo = max(cy0 - 1, 0), yhi = min(cy0 + 1, GW - 1);
        int xlo = max(cx0 - 1, 0), xhi = min(cx0 + 1, GW - 1);
        for (int cy = ylo; cy <= yhi; ++cy)
            for (int cx = xlo; cx <= xhi; ++cx)
                scanCell(cy * GW + cx, lane, gx, gy, gg, bm, newBits, best);
        best = warpMin(best);

        float bk0 = __uint_as_float((unsigned)(best >> 32));
        if (!(bk0 < 62.0f)) {                 // fallback (essentially never)
            for (int k = 2; k < GW; ++k) {
                int x0 = cx0 - k, x1 = cx0 + k, y0 = cy0 - k, y1 = cy0 + k;
                int yl = max(y0, 0), yh = min(y1, GW - 1);
                for (int cy = yl; cy <= yh; ++cy) {
                    bool edgeRow = (cy == y0 || cy == y1);
                    int xl = max(x0, 0), xh = min(x1, GW - 1);
                    for (int cx = xl; cx <= xh; ++cx) {
                        if (!edgeRow && cx != x0 && cx != x1) continue;
                        scanCell(cy * GW + cx, lane, gx, gy, gg, bm, newBits, best);
                    }
                }
                best = warpMin(best);
                float bk = __uint_as_float((unsigned)(best >> 32));
                float tt = 8.0f * (float)k;
                if (bk < tt * tt - 2.0f) break;
            }
        }
        #pragma unroll
        for (int o = 16; o; o >>= 1) newBits += __shfl_down_sync(0xffffffffu, newBits, o);
        if (lane == 0) {
            g_best[warpId] = best;
            atomicAdd(&g_cnt[img], newBits);
        }
    }
    gridBarrier();

    // ---- phase 3: finalize (block 0 only; one warp per image) ----
    if (b != 0) return;
    __shared__ int   s_asg[Bn][Mg], s_cls[Bn][Mg], s_srt[Bn][Mg];
    __shared__ float s_gtb[Bn][Mg][4];
    __shared__ double s_lc[Bn], s_lb[Bn];

    int w = t >> 5, lane = t & 31;
    if (w < 8) {
        int g = w;   // warp w -> image g

        for (int m = lane; m < Mg; m += 32) {
            s_asg[g][m] = (int)(unsigned)(g_best[g * Mg + m] & 0xFFFFFFFFULL);
            int l = gt_labels[g * Mg + m] - 1;
            s_cls[g][m] = min(max(l, 0), Cc - 1);
            #pragma unroll
            for (int j = 0; j < 4; j++) s_gtb[g][m][j] = gt_boxes[(g * Mg + m) * 4 + j];
        }
        __syncwarp();

        double corr = 0.0, posW = 0.0, ne = 0.0, eq = 0.0;
        int dis = 0;
        for (int m = lane; m < Mg; m += 32) {
            int a = s_asg[g][m], c = s_cls[g][m];
            bool dupA = false, dupAC = false;
            for (int u = 0; u < m; u++) {
                int au = s_asg[g][u];
                if (au == a) { dupA = true; if (s_cls[g][u] == c) dupAC = true; }
            }
            if (!dupA) {
                dis++;
                unsigned bit = (g_nonneg[g * NWORDS + (a >> 5)] >> (a & 31)) & 1u;
                posW += bit ? 0.1 : 1.0;
            }
            if (!dupAC)
                corr += (double)cls[((size_t)g * NA + a) * Cc + c];
            int rank = 0;
            for (int u = 0; u < Mg; u++) {
                int au = s_asg[g][u];
                if (au < a || (au == a && u < m)) rank++;
            }
            s_srt[g][rank] = a;
            float bx[4];
            computeBox(a, g, pred_reg, anchors, strides, bx);
            ne += (double)giouLoss(bx, s_gtb[g][m]);
        }
        __syncwarp();
        for (int m = lane; m < Mg; m += 32) {
            float bx[4];
            computeBox(s_srt[g][m], g, pred_reg, anchors, strides, bx);
            eq += (double)giouLoss(bx, s_gtb[g][m]);
        }

        // bce partials for image g: blocks g + 8*li, li = 0..36
        double bce = g_bcePart[g + 8 * lane];
        if (lane < 5) bce += g_bcePart[g + 8 * (lane + 32)];

        #pragma unroll
        for (int o = 16; o; o >>= 1) {
            corr += __shfl_down_sync(0xffffffffu, corr, o);
            posW += __shfl_down_sync(0xffffffffu, posW, o);
            ne   += __shfl_down_sync(0xffffffffu, ne, o);
            eq   += __shfl_down_sync(0xffffffffu, eq, o);
            bce  += __shfl_down_sync(0xffffffffu, bce, o);
            dis  += __shfl_down_sync(0xffffffffu, dis, o);
        }
        if (lane == 0) {
            int cnt = g_cnt[g];
            double sumSw = (double)(NA - cnt) + 0.1 * (double)cnt + posW;
            double meanSw = sumSw / (double)NA;
            double bceMean = (bce - corr) / ((double)NA * (double)Cc);
            s_lc[g] = bceMean * meanSw;
            s_lb[g] = (dis == Mg ? eq : ne) * 0.01;
        }
    }
    __syncthreads();
    if (t == 0) {
        double lc = 0.0, lb = 0.0;
        #pragma unroll
        for (int i = 0; i < Bn; i++) { lc += s_lc[i]; lb += s_lb[i]; }
        out[0] = (float)(lc / (double)Bn + 2.0 * (lb / (double)Bn));
    }
}

// ------------------------------------------------------------------
extern "C" void kernel_launch(void* const* d_in, const int* in_sizes, int n_in,
                              void* d_out, int out_size) {
    const float* pred_cls  = (const float*)d_in[0];
    const float* pred_reg  = (const float*)d_in[1];
    const float* anchors   = (const float*)d_in[2];
    const float* strides   = (const float*)d_in[3];
    const float* gt_boxes  = (const float*)d_in[4];
    const int*   gt_labels = (const int*)d_in[5];
    float* out = (float*)d_out;

    k_all<<<NB, NT>>>((const float2*)anchors, anchors,
                      (const float4*)pred_cls, pred_cls,
                      pred_reg, strides, gt_boxes, gt_labels, out);
}

// round 7
// speedup vs baseline: 15.8105x; 1.1685x over previous
#include <cuda_runtime.h>

static constexpr int Bn = 8;
static constexpr int NA = 262144;
static constexpr int Mg = 100;
static constexpr int Cc = 7;
static constexpr int GW = 128;            // cell = 8.0 units over [0,1024)
static constexpr int NCELLS = GW * GW;    // 16384
static constexpr int NWORDS = NA / 32;    // 8192 words per image
static constexpr int CAP = 64;            // bucket capacity (Poisson(16), overflow ~1e-18)

static constexpr int NB = 296;            // 2 blocks/SM on 148 SMs -> co-resident
static constexpr int NT = 512;
static constexpr int NTHR = NB * NT;      // 151552

static constexpr int F4_IMG = NA * Cc / 4;     // 458752 float4 per image
static constexpr int CH_IMG = 112;             // chunks/image; chunk = 4096 f4 = 64KB
static constexpr int BCE_B0 = 50;              // first bce block
static constexpr int BCE_NBLK = 30;            // bce blocks per image (8*30 = 240)

// ---- device scratch (static zero-init; kernel leaves cnt arrays zeroed) ----
__device__ int                g_cellCnt[NCELLS];
__device__ float4             g_item[NCELLS * CAP];   // (x, y, bits(idx), 0)
__device__ unsigned int       g_nonneg[Bn * NWORDS];
__device__ unsigned long long g_best[Bn * Mg];
__device__ double             g_bcePart[NB];
__device__ int                g_cnt[Bn];
__device__ unsigned int          g_barCnt = 0;
__device__ volatile unsigned int g_barGen = 0;

// ---- software grid barrier (all NB blocks co-resident) ----
__device__ __forceinline__ void gridBarrier() {
    __syncthreads();
    if (threadIdx.x == 0) {
        unsigned gen = g_barGen;
        __threadfence();
        if (atomicAdd(&g_barCnt, 1u) == NB - 1) {
            g_barCnt = 0;
            __threadfence();
            g_barGen = gen + 1;
        } else {
            while (g_barGen == gen) __nanosleep(64);
        }
        __threadfence();
    }
    __syncthreads();
}

__device__ __forceinline__ int cellOf(float x) {
    int c = (int)(x * 0.125f);
    return min(GW - 1, max(0, c));
}

// ---- batched softplus: sum over 8 elems with ONE lg2 ----
// sum softplus(x_i) = sum max(x_i,0) + ln2 * lg2( prod (1 + 2^(-|x_i|*log2e)) )
// error budget ~2e-6 abs per group (systematic) -> ~1e-6 rel in final loss
__device__ __forceinline__ float ex2f(float x) {
    float r; asm("ex2.approx.f32 %0, %1;" : "=f"(r) : "f"(x)); return r;
}
__device__ __forceinline__ float lg2f(float x) {
    float r; asm("lg2.approx.f32 %0, %1;" : "=f"(r) : "f"(x)); return r;
}
__device__ __forceinline__ float sp8(float4 a, float4 b) {
    const float NL2E = -1.4426950408889634f;
    float w0 = 1.0f + ex2f(fabsf(a.x) * NL2E);
    float w1 = 1.0f + ex2f(fabsf(a.y) * NL2E);
    float w2 = 1.0f + ex2f(fabsf(a.z) * NL2E);
    float w3 = 1.0f + ex2f(fabsf(a.w) * NL2E);
    float w4 = 1.0f + ex2f(fabsf(b.x) * NL2E);
    float w5 = 1.0f + ex2f(fabsf(b.y) * NL2E);
    float w6 = 1.0f + ex2f(fabsf(b.z) * NL2E);
    float w7 = 1.0f + ex2f(fabsf(b.w) * NL2E);
    float p = ((w0 * w1) * (w2 * w3)) * ((w4 * w5) * (w6 * w7));   // in (1, 256]
    float m = (fmaxf(a.x, 0.f) + fmaxf(a.y, 0.f)) + (fmaxf(a.z, 0.f) + fmaxf(a.w, 0.f))
            + (fmaxf(b.x, 0.f) + fmaxf(b.y, 0.f)) + (fmaxf(b.z, 0.f) + fmaxf(b.w, 0.f));
    return fmaf(0.6931471805599453f, lg2f(p), m);
}

// d2 arithmetic replicates the reference bit-exactly (verified rel_err=0.0)
__device__ __forceinline__ void scanCell(
        int c, int lane, float gx, float gy, float gg,
        unsigned int* bm, int& newBits, unsigned long long& best) {
    int cnt = min(g_cellCnt[c], CAP);
    int base = c * CAP;
    for (int i = lane; i < cnt; i += 32) {
        float4 it = g_item[base + i];
        int n = __float_as_int(it.z);
        float aa  = __fadd_rn(__fmul_rn(it.x, it.x), __fmul_rn(it.y, it.y));
        float dot = __fmaf_rn(gy, it.y, __fmul_rn(gx, it.x));
        float d2  = __fsub_rn(__fadd_rn(gg, aa), __fadd_rn(dot, dot));
        if (d2 <= 9.0f) {
            unsigned bit = 1u << (n & 31);
            unsigned old = atomicOr(&bm[n >> 5], bit);
            if (!(old & bit)) newBits++;
        }
        float key = fmaxf(d2, 0.0f);
        unsigned long long pk =
            ((unsigned long long)__float_as_uint(key) << 32) | (unsigned)n;
        if (pk < best) best = pk;
    }
}

__device__ __forceinline__ unsigned long long warpMin(unsigned long long v) {
    #pragma unroll
    for (int off = 16; off; off >>= 1) {
        unsigned long long o = __shfl_xor_sync(0xffffffffu, v, off);
        if (o < v) v = o;
    }
    return v;
}

__device__ __forceinline__ void computeBox(int n, int b,
        const float* __restrict__ pred_reg, const float* __restrict__ anchors,
        const float* __restrict__ strides, float* box) {
    float s = strides[n];
    const float* r = &pred_reg[((size_t)b * NA + n) * 4];
    float ax = anchors[2 * n], ay = anchors[2 * n + 1];
    float cx = __fadd_rn(ax, __fmul_rn(r[0], s));
    float cy = __fadd_rn(ay, __fmul_rn(r[1], s));
    float w  = __fmul_rn(expf(r[2]), s);
    float h  = __fmul_rn(expf(r[3]), s);
    float w2 = __fmul_rn(w, 0.5f), h2 = __fmul_rn(h, 0.5f);
    box[0] = __fsub_rn(cx, w2);
    box[1] = __fsub_rn(cy, h2);
    box[2] = __fadd_rn(cx, w2);
    box[3] = __fadd_rn(cy, h2);
}

__device__ __forceinline__ float giouLoss(const float* p, const float* g) {
    const float EPS = 1e-7f;
    float ap = __fmul_rn(__fsub_rn(p[2], p[0]), __fsub_rn(p[3], p[1]));
    float ag = __fmul_rn(__fsub_rn(g[2], g[0]), __fsub_rn(g[3], g[1]));
    float ltx = fmaxf(p[0], g[0]), lty = fmaxf(p[1], g[1]);
    float rbx = fminf(p[2], g[2]), rby = fminf(p[3], g[3]);
    float wx = fmaxf(__fsub_rn(rbx, ltx), 0.f), wy = fmaxf(__fsub_rn(rby, lty), 0.f);
    float inter = __fmul_rn(wx, wy);
    float uni = __fsub_rn(__fadd_rn(ap, ag), inter);
    float iou = __fdiv_rn(inter, __fadd_rn(uni, EPS));
    float lcx = fminf(p[0], g[0]), lcy = fminf(p[1], g[1]);
    float rcx = fmaxf(p[2], g[2]), rcy = fmaxf(p[3], g[3]);
    float wcx = fmaxf(__fsub_rn(rcx, lcx), 0.f), wcy = fmaxf(__fsub_rn(rcy, lcy), 0.f);
    float ac = __fmul_rn(wcx, wcy);
    float giou = __fsub_rn(iou, __fdiv_rn(__fsub_rn(ac, uni), __fadd_rn(ac, EPS)));
    return __fsub_rn(1.0f, giou);
}

// ==================================================================
__global__ void __launch_bounds__(NT, 2) k_all(
        const float2* __restrict__ anchors2, const float* __restrict__ anchors,
        const float4* __restrict__ cls4,     const float* __restrict__ cls,
        const float* __restrict__ pred_reg,  const float* __restrict__ strides,
        const float* __restrict__ gt_boxes,  const int* __restrict__ gt_labels,
        float* __restrict__ out) {
    const int b = blockIdx.x, t = threadIdx.x;
    const int gid = b * NT + t;

    // ---- phase A: scatter anchors (cellCnt zeroed by previous call / static init)
    //      + zero the non-neg bitmap for this call ----
    for (int n = gid; n < NA; n += NTHR) {
        float2 a = anchors2[n];
        int cell = cellOf(a.y) * GW + cellOf(a.x);
        int p = atomicAdd(&g_cellCnt[cell], 1);
        if (p < CAP) g_item[cell * CAP + p] = make_float4(a.x, a.y, __int_as_float(n), 0.f);
    }
    for (int i = gid; i < Bn * NWORDS; i += NTHR) g_nonneg[i] = 0u;
    gridBarrier();

    // ---- phase B: assign (blocks 0..49)  ||  bce stream (blocks 50..289) ----
    if (b < BCE_B0) {
        // one warp per (img, gt)
        int warpId = b * 16 + (t >> 5);       // 0..799
        int lane = t & 31;
        int img = warpId / Mg, m = warpId % Mg;

        const float* g = &gt_boxes[(img * Mg + m) * 4];
        float gx = __fmul_rn(__fadd_rn(g[0], g[2]), 0.5f);
        float gy = __fmul_rn(__fadd_rn(g[1], g[3]), 0.5f);
        float gg = __fadd_rn(__fmul_rn(gx, gx), __fmul_rn(gy, gy));
        int cx0 = cellOf(gx), cy0 = cellOf(gy);
        unsigned int* bm = &g_nonneg[img * NWORDS];

        int newBits = 0;
        unsigned long long best = 0xFFFFFFFFFFFFFFFFULL;
        int ylo = max(cy0 - 1, 0), yhi = min(cy0 + 1, GW - 1);
        int xlo = max(cx0 - 1, 0), xhi = min(cx0 + 1, GW - 1);
        for (int cy = ylo; cy <= yhi; ++cy)
            for (int cx = xlo; cx <= xhi; ++cx)
                scanCell(cy * GW + cx, lane, gx, gy, gg, bm, newBits, best);
        best = warpMin(best);

        float bk0 = __uint_as_float((unsigned)(best >> 32));
        if (!(bk0 < 62.0f)) {                 // fallback (essentially never)
            for (int k = 2; k < GW; ++k) {
                int x0 = cx0 - k, x1 = cx0 + k, y0 = cy0 - k, y1 = cy0 + k;
                int yl = max(y0, 0), yh = min(y1, GW - 1);
                for (int cy = yl; cy <= yh; ++cy) {
                    bool edgeRow = (cy == y0 || cy == y1);
                    int xl = max(x0, 0), xh = min(x1, GW - 1);
                    for (int cx = xl; cx <= xh; ++cx) {
                        if (!edgeRow && cx != x0 && cx != x1) continue;
                        scanCell(cy * GW + cx, lane, gx, gy, gg, bm, newBits, best);
                    }
                }
                best = warpMin(best);
                float bk = __uint_as_float((unsigned)(best >> 32));
                float tt = 8.0f * (float)k;
                if (bk < tt * tt - 2.0f) break;
            }
        }
        #pragma unroll
        for (int o = 16; o; o >>= 1) newBits += __shfl_down_sync(0xffffffffu, newBits, o);
        if (lane == 0) {
            g_best[warpId] = best;
            atomicAdd(&g_cnt[img], newBits);
        }
    } else if (b < BCE_B0 + Bn * BCE_NBLK) {
        // bce: 240 blocks, 30 per image; chunks c = li, li+30, ... < 112
        __shared__ double shb[16];
        int idx = b - BCE_B0;
        int img = idx & 7, li = idx >> 3;     // li in [0, 30)
        const float4* base = cls4 + (size_t)img * F4_IMG;
        double acc = 0.0;
        for (int c = li; c < CH_IMG; c += BCE_NBLK) {
            const float4* p = base + c * 4096 + t;
            float4 v[8];
            #pragma unroll
            for (int j = 0; j < 8; j++)       // 8 coalesced LDG.128 in flight
                v[j] = p[j * 512];
            float a0 = (sp8(v[0], v[1]) + sp8(v[2], v[3]))
                     + (sp8(v[4], v[5]) + sp8(v[6], v[7]));
            acc += (double)a0;
        }
        #pragma unroll
        for (int o = 16; o; o >>= 1) acc += __shfl_down_sync(0xffffffffu, acc, o);
        if ((t & 31) == 0) shb[t >> 5] = acc;
        __syncthreads();
        if (t == 0) {
            double s = 0.0;
            #pragma unroll
            for (int j = 0; j < 16; j++) s += shb[j];
            g_bcePart[b] = s;
        }
    }
    gridBarrier();

    // ---- phase C: block 0 finalizes; other blocks zero cellCnt for next call ----
    if (b != 0) {
        for (int i = (b - 1) * NT + t; i < NCELLS; i += (NB - 1) * NT)
            g_cellCnt[i] = 0;
        return;
    }

    __shared__ int   s_asg[Bn][Mg], s_cls[Bn][Mg], s_srt[Bn][Mg];
    __shared__ float s_gtb[Bn][Mg][4];
    __shared__ double s_lc[Bn], s_lb[Bn];

    int w = t >> 5, lane = t & 31;
    if (w < 8) {
        int g = w;   // warp w -> image g

        for (int m = lane; m < Mg; m += 32) {
            s_asg[g][m] = (int)(unsigned)(g_best[g * Mg + m] & 0xFFFFFFFFULL);
            int l = gt_labels[g * Mg + m] - 1;
            s_cls[g][m] = min(max(l, 0), Cc - 1);
            #pragma unroll
            for (int j = 0; j < 4; j++) s_gtb[g][m][j] = gt_boxes[(g * Mg + m) * 4 + j];
        }
        __syncwarp();

        double corr = 0.0, posW = 0.0, ne = 0.0, eq = 0.0;
        int dis = 0;
        for (int m = lane; m < Mg; m += 32) {
            int a = s_asg[g][m], c = s_cls[g][m];
            bool dupA = false, dupAC = false;
            for (int u = 0; u < m; u++) {
                int au = s_asg[g][u];
                if (au == a) { dupA = true; if (s_cls[g][u] == c) dupAC = true; }
            }
            if (!dupA) {
                dis++;
                unsigned bit = (g_nonneg[g * NWORDS + (a >> 5)] >> (a & 31)) & 1u;
                posW += bit ? 0.1 : 1.0;
            }
            if (!dupAC)
                corr += (double)cls[((size_t)g * NA + a) * Cc + c];
            int rank = 0;
            for (int u = 0; u < Mg; u++) {
                int au = s_asg[g][u];
                if (au < a || (au == a && u < m)) rank++;
            }
            s_srt[g][rank] = a;
            float bx[4];
            computeBox(a, g, pred_reg, anchors, strides, bx);
            ne += (double)giouLoss(bx, s_gtb[g][m]);
        }
        __syncwarp();
        for (int m = lane; m < Mg; m += 32) {
            float bx[4];
            computeBox(s_srt[g][m], g, pred_reg, anchors, strides, bx);
            eq += (double)giouLoss(bx, s_gtb[g][m]);
        }

        // bce partials for image g at blocks BCE_B0 + g + 8*li, li = 0..29
        double bce = (lane < BCE_NBLK) ? g_bcePart[BCE_B0 + g + 8 * lane] : 0.0;

        #pragma unroll
        for (int o = 16; o; o >>= 1) {
            corr += __shfl_down_sync(0xffffffffu, corr, o);
            posW += __shfl_down_sync(0xffffffffu, posW, o);
            ne   += __shfl_down_sync(0xffffffffu, ne, o);
            eq   += __shfl_down_sync(0xffffffffu, eq, o);
            bce  += __shfl_down_sync(0xffffffffu, bce, o);
            dis  += __shfl_down_sync(0xffffffffu, dis, o);
        }
        if (lane == 0) {
            int cnt = g_cnt[g];
            double sumSw = (double)(NA - cnt) + 0.1 * (double)cnt + posW;
            double meanSw = sumSw / (double)NA;
            double bceMean = (bce - corr) / ((double)NA * (double)Cc);
            s_lc[g] = bceMean * meanSw;
            s_lb[g] = (dis == Mg ? eq : ne) * 0.01;
        }
    }
    __syncthreads();
    if (t == 0) {
        double lc = 0.0, lb = 0.0;
        #pragma unroll
        for (int i = 0; i < Bn; i++) { lc += s_lc[i]; lb += s_lb[i]; }
        out[0] = (float)(lc / (double)Bn + 2.0 * (lb / (double)Bn));
    }
    if (t < Bn) g_cnt[t] = 0;   // leave zeroed for next call
}

// ------------------------------------------------------------------
extern "C" void kernel_launch(void* const* d_in, const int* in_sizes, int n_in,
                              void* d_out, int out_size) {
    const float* pred_cls  = (const float*)d_in[0];
    const float* pred_reg  = (const float*)d_in[1];
    const float* anchors   = (const float*)d_in[2];
    const float* strides   = (const float*)d_in[3];
    const float* gt_boxes  = (const float*)d_in[4];
    const int*   gt_labels = (const int*)d_in[5];
    float* out = (float*)d_out;

    k_all<<<NB, NT>>>((const float2*)anchors, anchors,
                      (const float4*)pred_cls, pred_cls,
                      pred_reg, strides, gt_boxes, gt_labels, out);
}